// round 5
// baseline (speedup 1.0000x reference)
#include <cuda_runtime.h>
#include <math.h>

#define NN 200
#define DD 128
#define HH 4
#define PAD_IDX 100000

// ---------------- device scratch (no runtime allocation allowed) ----------------
__device__ float g_K[2048u * 4u * 200u * 128u];     // ~839 MB
__device__ float g_Q[2048u * 4u * 200u * 128u];     // ~839 MB
__device__ float g_w[2048u * 4u * 200u];            // softmax column sums
__device__ float g_Wt[256 * 1024];                  // [f][o] transposed K|Q weights
__device__ float g_Wcomb[4 * 256 * 128];            // [h][f][d] Wv folded with Ww
__device__ float g_WheadT[128 * 128];               // [e][d] Whead transposed

// ---------------- prep kernels ----------------
__global__ void prep_wt(const float* __restrict__ Wk, const float* __restrict__ Wq) {
    int f = blockIdx.x;
    for (int o = threadIdx.x; o < 1024; o += blockDim.x) {
        int kq = o >> 9, h = (o >> 7) & 3, d = o & 127;
        const float* W = kq ? Wq : Wk;
        g_Wt[f * 1024 + o] = W[(h * 128 + d) * 256 + f];
    }
}

__global__ void prep_wcomb(const float* __restrict__ Wv, const float* __restrict__ Ww) {
    int f = blockIdx.x, h = blockIdx.y, d2 = threadIdx.x;
    float a = 0.f;
    for (int d = 0; d < 128; d++)
        a = fmaf(Wv[(h * 128 + d) * 256 + f], Ww[d2 * 512 + h * 128 + d], a);
    g_Wcomb[(h * 256 + f) * 128 + d2] = a;
}

__global__ void prep_wheadT(const float* __restrict__ Whead) {
    g_WheadT[blockIdx.x * 128 + threadIdx.x] = Whead[threadIdx.x * 128 + blockIdx.x];
}

// ---------------- kernel 1: K,Q projections ----------------
// One CTA per (b,side). X (200x256 fp32, rows padded to 65 float4) in SMEM.
// 16 warps; each warp owns 64 output cols (lane -> o1, o1+32), 25-row blocking.
__global__ void __launch_bounds__(512, 1)
proj_kernel(const int* __restrict__ lconn, const int* __restrict__ rconn,
            const float* __restrict__ emb) {
    extern __shared__ float smem_f[];
    float4* Xs4 = reinterpret_cast<float4*>(smem_f);   // [200][65]
    int sid = blockIdx.x;
    int b = sid >> 1;
    const int* conn = (sid & 1) ? rconn : lconn;

    // gather concat(emb[rel], emb[ent]) rows: 200 rows x 64 float4
    for (int i = threadIdx.x; i < 200 * 64; i += 512) {
        int n = i >> 6, q = i & 63;
        int idx = conn[(b * NN + n) * 2 + (q >> 5)];
        Xs4[n * 65 + q] = reinterpret_cast<const float4*>(emb + (size_t)idx * DD)[q & 31];
    }
    __syncthreads();

    int warp = threadIdx.x >> 5, lane = threadIdx.x & 31;
    int o1 = warp * 64 + lane;
    int o2 = o1 + 32;
    const float* wt1 = g_Wt + o1;
    const float* wt2 = g_Wt + o2;
    int kq = o1 >> 9, h = (o1 >> 7) & 3;
    float* gbase = (kq ? g_Q : g_K) + (size_t)(sid * HH + h) * NN * DD;
    int d1 = o1 & 127, d2o = o2 & 127;

    for (int rt = 0; rt < 8; rt++) {
        int n0 = rt * 25;
        float acc0[25], acc1[25];
#pragma unroll
        for (int r = 0; r < 25; r++) { acc0[r] = 0.f; acc1[r] = 0.f; }

        float cw0[4], cw1[4];
#pragma unroll
        for (int k = 0; k < 4; k++) { cw0[k] = wt1[k * 1024]; cw1[k] = wt2[k * 1024]; }

        for (int f4 = 0; f4 < 64; f4++) {
            int fn = (f4 + 1 < 64) ? (f4 + 1) : 63;
            float nw0[4], nw1[4];
#pragma unroll
            for (int k = 0; k < 4; k++) {
                nw0[k] = wt1[(fn * 4 + k) * 1024];
                nw1[k] = wt2[(fn * 4 + k) * 1024];
            }
#pragma unroll
            for (int r = 0; r < 25; r++) {
                float4 xv = Xs4[(n0 + r) * 65 + f4];
                acc0[r] = fmaf(xv.x, cw0[0], acc0[r]);
                acc0[r] = fmaf(xv.y, cw0[1], acc0[r]);
                acc0[r] = fmaf(xv.z, cw0[2], acc0[r]);
                acc0[r] = fmaf(xv.w, cw0[3], acc0[r]);
                acc1[r] = fmaf(xv.x, cw1[0], acc1[r]);
                acc1[r] = fmaf(xv.y, cw1[1], acc1[r]);
                acc1[r] = fmaf(xv.z, cw1[2], acc1[r]);
                acc1[r] = fmaf(xv.w, cw1[3], acc1[r]);
            }
#pragma unroll
            for (int k = 0; k < 4; k++) { cw0[k] = nw0[k]; cw1[k] = nw1[k]; }
        }
#pragma unroll
        for (int r = 0; r < 25; r++) {
            gbase[(size_t)(n0 + r) * DD + d1]  = acc0[r];
            gbase[(size_t)(n0 + r) * DD + d2o] = acc1[r];
        }
    }
}

// ---------------- kernel 2: scores + softmax + column sums ----------------
// One CTA per (b,side,head). K [200][128] + Q^T [128][225-padded] in SMEM.
// Each warp handles row pairs; lane covers m = lane + 32j, j<7 (m padded to 224).
#define QTS 225
__global__ void __launch_bounds__(512, 1)
attn_kernel(const int* __restrict__ lconn, const int* __restrict__ rconn) {
    extern __shared__ float smem_f[];
    float* Ks  = smem_f;               // 25600
    float* Qt  = smem_f + 25600;       // 128*225 = 28800
    float* ws  = Qt + 28800;           // 224
    float* msk = ws + 224;             // 224

    int sid = blockIdx.x, h = blockIdx.y;
    int b = sid >> 1;
    const int* conn = (sid & 1) ? rconn : lconn;
    const float* Kg = g_K + (size_t)(sid * HH + h) * NN * DD;
    const float* Qg = g_Q + (size_t)(sid * HH + h) * NN * DD;
    int tid = threadIdx.x;

    for (int i = tid; i < 6400; i += 512)
        reinterpret_cast<float4*>(Ks)[i] = reinterpret_cast<const float4*>(Kg)[i];
    for (int i = tid; i < 25600; i += 512) {
        int m = i >> 7, d = i & 127;
        Qt[d * QTS + m] = Qg[i];
    }
    for (int i = tid; i < 128 * 24; i += 512) {   // zero-pad cols 200..223
        int d = i / 24, m = 200 + (i - d * 24);
        Qt[d * QTS + m] = 0.f;
    }
    for (int i = tid; i < 224; i += 512) {
        ws[i] = 0.f;
        msk[i] = (i < 200) ? ((conn[(b * NN + i) * 2] == PAD_IDX) ? 1.f : 0.f) : 1.f;
    }
    __syncthreads();

    int warp = tid >> 5, lane = tid & 31;
    float mj[7];
#pragma unroll
    for (int j = 0; j < 7; j++) mj[j] = msk[lane + 32 * j];
    const float scale = 0.08838834764831845f;  // 128^-0.5

    float wacc[7];
#pragma unroll
    for (int j = 0; j < 7; j++) wacc[j] = 0.f;

    for (int base = warp * 2; base < 200; base += 32) {
        const float4* Ka = reinterpret_cast<const float4*>(Ks + base * DD);
        const float4* Kb = reinterpret_cast<const float4*>(Ks + (base + 1) * DD);
        float acca[7], accb[7];
#pragma unroll
        for (int j = 0; j < 7; j++) { acca[j] = 0.f; accb[j] = 0.f; }

        for (int d4 = 0; d4 < 32; d4++) {
            float4 ka = Ka[d4], kb = Kb[d4];
            const float* q0 = Qt + (d4 * 4) * QTS + lane;
#pragma unroll
            for (int j = 0; j < 7; j++) {
                float qv0 = q0[32 * j];
                float qv1 = q0[QTS + 32 * j];
                float qv2 = q0[2 * QTS + 32 * j];
                float qv3 = q0[3 * QTS + 32 * j];
                acca[j] = fmaf(ka.x, qv0, acca[j]);
                accb[j] = fmaf(kb.x, qv0, accb[j]);
                acca[j] = fmaf(ka.y, qv1, acca[j]);
                accb[j] = fmaf(kb.y, qv1, accb[j]);
                acca[j] = fmaf(ka.z, qv2, acca[j]);
                accb[j] = fmaf(kb.z, qv2, accb[j]);
                acca[j] = fmaf(ka.w, qv3, acca[j]);
                accb[j] = fmaf(kb.w, qv3, accb[j]);
            }
        }
#pragma unroll
        for (int rr = 0; rr < 2; rr++) {
            float rowm = msk[base + rr];
            float sa[7];
#pragma unroll
            for (int j = 0; j < 7; j++) {
                int m = lane + 32 * j;
                float s = (rr ? accb[j] : acca[j]) * scale;
                if (rowm > 0.5f || mj[j] > 0.5f) s = -1e9f;
                if (m >= 200) s = -1e30f;      // pad cols -> exp underflows to 0
                sa[j] = s;
            }
            float rmax = sa[0];
#pragma unroll
            for (int j = 1; j < 7; j++) rmax = fmaxf(rmax, sa[j]);
#pragma unroll
            for (int off = 16; off; off >>= 1)
                rmax = fmaxf(rmax, __shfl_xor_sync(0xffffffffu, rmax, off));
            float e[7], Z = 0.f;
#pragma unroll
            for (int j = 0; j < 7; j++) { e[j] = expf(sa[j] - rmax); Z += e[j]; }
#pragma unroll
            for (int off = 16; off; off >>= 1)
                Z += __shfl_xor_sync(0xffffffffu, Z, off);
            float inv = 1.f / Z;
#pragma unroll
            for (int j = 0; j < 7; j++) wacc[j] = fmaf(e[j], inv, wacc[j]);
        }
    }
#pragma unroll
    for (int j = 0; j < 7; j++) {
        int m = lane + 32 * j;
        if (m < 200) atomicAdd(ws + m, wacc[j]);
    }
    __syncthreads();
    for (int i = tid; i < 200; i += 512)
        g_w[(size_t)sid * 800 + h * 200 + i] = ws[i];
}

// ---------------- kernel 3: y = w^T X, folded projections, relu, residual, LN ----
__global__ void __launch_bounds__(256)
final_kernel(const int* __restrict__ ep, const int* __restrict__ lconn,
             const int* __restrict__ rconn, const float* __restrict__ emb,
             const float* __restrict__ lnw, const float* __restrict__ lnb,
             float* __restrict__ out) {
    __shared__ float wsm[4 * 200];
    __shared__ int reli[200], enti[200];
    __shared__ float es[128];
    __shared__ float ys[4][256];
    __shared__ float redbuf[8];

    int sid = blockIdx.x;
    int b = sid >> 1, side = sid & 1;
    const int* conn = side ? rconn : lconn;
    int tid = threadIdx.x;

    for (int i = tid; i < 200; i += 256) {
        int2 c = reinterpret_cast<const int2*>(conn)[b * NN + i];
        reli[i] = c.x; enti[i] = c.y;
    }
    for (int i = tid; i < 800; i += 256) wsm[i] = g_w[(size_t)sid * 800 + i];
    if (tid < 128) es[tid] = emb[(size_t)ep[b * 2 + side] * DD + tid];
    __syncthreads();

    {   // y_h[f] = sum_m w_h[m] * X[m][f],  f = tid in [0,256)
        float a0 = 0.f, a1 = 0.f, a2 = 0.f, a3 = 0.f;
        bool lo = tid < 128;
        int fo = tid & 127;
        for (int m = 0; m < 200; m++) {
            int row = lo ? reli[m] : enti[m];
            float x = emb[(size_t)row * DD + fo];
            a0 = fmaf(wsm[m],       x, a0);
            a1 = fmaf(wsm[200 + m], x, a1);
            a2 = fmaf(wsm[400 + m], x, a2);
            a3 = fmaf(wsm[600 + m], x, a3);
        }
        ys[0][tid] = a0; ys[1][tid] = a1; ys[2][tid] = a2; ys[3][tid] = a3;
    }
    __syncthreads();

    float tval = 0.f;
    if (tid < 128) {
        int d = tid;
        float pa = 0.f;
#pragma unroll
        for (int hh = 0; hh < 4; hh++) {
            const float* wc = g_Wcomb + (size_t)(hh * 256) * 128 + d;
            const float* yy = ys[hh];
            for (int ff = 0; ff < 256; ff++)
                pa = fmaf(yy[ff], wc[ff * 128], pa);
        }
        float ht = 0.f;
        for (int e = 0; e < 128; e++) ht = fmaf(es[e], g_WheadT[e * 128 + d], ht);
        tval = fmaxf(pa + ht, 0.f) + es[d];
    }

    // LayerNorm over 128 values (threads >=128 contribute zeros; divide by 128)
    int lane = tid & 31, warp = tid >> 5;
    float v = tval;
#pragma unroll
    for (int off = 16; off; off >>= 1) v += __shfl_xor_sync(0xffffffffu, v, off);
    if (lane == 0) redbuf[warp] = v;
    __syncthreads();
    float tot = 0.f;
#pragma unroll
    for (int w2 = 0; w2 < 8; w2++) tot += redbuf[w2];
    float mu = tot * (1.f / 128.f);
    __syncthreads();

    float diff = (tid < 128) ? (tval - mu) : 0.f;
    float v2 = diff * diff;
#pragma unroll
    for (int off = 16; off; off >>= 1) v2 += __shfl_xor_sync(0xffffffffu, v2, off);
    if (lane == 0) redbuf[warp] = v2;
    __syncthreads();
    float tot2 = 0.f;
#pragma unroll
    for (int w2 = 0; w2 < 8; w2++) tot2 += redbuf[w2];
    float var = tot2 * (1.f / 128.f);

    if (tid < 128)
        out[(size_t)sid * 128 + tid] =
            diff * rsqrtf(var + 1e-5f) * lnw[tid] + lnb[tid];
}

// ---------------- launch ----------------
extern "C" void kernel_launch(void* const* d_in, const int* in_sizes, int n_in,
                              void* d_out, int out_size) {
    const int*   ep    = (const int*)d_in[0];
    const int*   lconn = (const int*)d_in[1];
    const int*   rconn = (const int*)d_in[3];
    const float* emb   = (const float*)d_in[5];
    const float* Wv    = (const float*)d_in[6];
    const float* Wk    = (const float*)d_in[7];
    const float* Wq    = (const float*)d_in[8];
    const float* Ww    = (const float*)d_in[9];
    const float* Whead = (const float*)d_in[10];
    const float* lnw   = (const float*)d_in[11];
    const float* lnb   = (const float*)d_in[12];
    float* out = (float*)d_out;

    const int B = in_sizes[0] / 2;          // 1024
    const int SIDES = 2 * B;                // 2048

    static bool attr_done = false;          // idempotent attribute set (not work)
    if (!attr_done) {
        cudaFuncSetAttribute(proj_kernel, cudaFuncAttributeMaxDynamicSharedMemorySize,
                             200 * 65 * 16);
        cudaFuncSetAttribute(attn_kernel, cudaFuncAttributeMaxDynamicSharedMemorySize,
                             (25600 + 128 * QTS + 224 + 224) * 4);
        attr_done = true;
    }

    prep_wt   <<<256, 256>>>(Wk, Wq);
    prep_wcomb<<<dim3(256, 4), 128>>>(Wv, Ww);
    prep_wheadT<<<128, 128>>>(Whead);

    proj_kernel<<<SIDES, 512, 200 * 65 * 16>>>(lconn, rconn, emb);
    attn_kernel<<<dim3(SIDES, 4), 512, (25600 + 128 * QTS + 224 + 224) * 4>>>(lconn, rconn);
    final_kernel<<<SIDES, 256>>>(ep, lconn, rconn, emb, lnw, lnb, out);
}

// round 7
// speedup vs baseline: 3.9151x; 3.9151x over previous
#include <cuda_runtime.h>
#include <cuda_bf16.h>
#include <math.h>
#include <stdint.h>

#define NN 200
#define DD 128
#define HH 4
#define PAD_IDX 100000
#define VP1 100001

// ---------------- device scratch (no runtime allocation allowed) ----------------
__device__ __nv_bfloat16 g_Kb[2048u * 4u * 200u * 128u];   // 420 MB bf16 K
__device__ __nv_bfloat16 g_Qb[2048u * 4u * 200u * 128u];   // 420 MB bf16 Q
__device__ float g_w[2048u * 4u * 200u];                   // softmax column sums
__device__ float g_Wcomb[4 * 256 * 128];                   // [h][f][d] Wv folded with Ww
__device__ float g_WheadT[128 * 128];                      // [e][d] Whead transposed
__device__ __nv_bfloat16 g_Wb[8 * 128 * 256];              // [kq*4+h][o][f] bf16 W
__device__ __nv_bfloat16 g_embB[(size_t)VP1 * 128];        // bf16 embeddings

// ================= helpers =================
__device__ __forceinline__ uint32_t smem_u32(const void* p) {
    uint32_t a;
    asm("{ .reg .u64 t; cvta.to.shared.u64 t, %1; cvt.u32.u64 %0, t; }" : "=r"(a) : "l"(p));
    return a;
}
__device__ __forceinline__ void ldsm_x4(uint32_t* r, uint32_t a) {
    asm volatile("ldmatrix.sync.aligned.m8n8.x4.shared.b16 {%0,%1,%2,%3}, [%4];"
                 : "=r"(r[0]), "=r"(r[1]), "=r"(r[2]), "=r"(r[3]) : "r"(a));
}
__device__ __forceinline__ void ldsm_x2(uint32_t* r, uint32_t a) {
    asm volatile("ldmatrix.sync.aligned.m8n8.x2.shared.b16 {%0,%1}, [%2];"
                 : "=r"(r[0]), "=r"(r[1]) : "r"(a));
}
__device__ __forceinline__ void mma_bf16(float* c, const uint32_t* a, const uint32_t* b) {
    asm volatile("mma.sync.aligned.m16n8k16.row.col.f32.bf16.bf16.f32 "
                 "{%0,%1,%2,%3}, {%4,%5,%6,%7}, {%8,%9}, {%0,%1,%2,%3};"
                 : "+f"(c[0]), "+f"(c[1]), "+f"(c[2]), "+f"(c[3])
                 : "r"(a[0]), "r"(a[1]), "r"(a[2]), "r"(a[3]), "r"(b[0]), "r"(b[1]));
}
__device__ __forceinline__ uint32_t pack_bf2(float x, float y) {
    __nv_bfloat162 h = __floats2bfloat162_rn(x, y);
    return *reinterpret_cast<uint32_t*>(&h);
}

// ---------------- prep kernels ----------------
__global__ void prep_wcomb(const float* __restrict__ Wv, const float* __restrict__ Ww) {
    int f = blockIdx.x, h = blockIdx.y, d2 = threadIdx.x;
    float a = 0.f;
    for (int d = 0; d < 128; d++)
        a = fmaf(Wv[(h * 128 + d) * 256 + f], Ww[d2 * 512 + h * 128 + d], a);
    g_Wcomb[(h * 256 + f) * 128 + d2] = a;
}
__global__ void prep_wheadT(const float* __restrict__ Whead) {
    g_WheadT[blockIdx.x * 128 + threadIdx.x] = Whead[threadIdx.x * 128 + blockIdx.x];
}
__global__ void prep_wbf16(const float* __restrict__ Wk, const float* __restrict__ Wq) {
    int i = blockIdx.x * 256 + threadIdx.x;   // grid 1024 -> 262144
    g_Wb[i] = __float2bfloat16(i < 131072 ? Wk[i] : Wq[i - 131072]);
}
__global__ void prep_embB(const float* __restrict__ emb) {
    int i = blockIdx.x * 256 + threadIdx.x;
    if (i < VP1 * 128) g_embB[i] = __float2bfloat16(emb[i]);
}

// ---------------- kernel 1: K,Q projections via mma.sync bf16 ----------------
// CTA = (b,side), 416 threads = 13 warps. Xs [208][264] bf16, Ws [128][264] bf16.
// Warp w handles M-tile w (16 rows). Loop 8 N-tiles of 128 (kq,h).
#define XS 264
#define SMP_WS_OFF 109824   // 208*264*2
#define SMP_TOTAL  177408   // + 128*264*2
__global__ void __launch_bounds__(416, 1)
proj_hmma(const int* __restrict__ lconn, const int* __restrict__ rconn) {
    extern __shared__ char smem[];
    __nv_bfloat16* Xs = reinterpret_cast<__nv_bfloat16*>(smem);
    char* WsB = smem + SMP_WS_OFF;
    uint32_t sX = smem_u32(smem);
    uint32_t sW = sX + SMP_WS_OFF;

    int tid = threadIdx.x, w = tid >> 5, lane = tid & 31;
    int sid = blockIdx.x, b = sid >> 1;
    const int* conn = (sid & 1) ? rconn : lconn;

    // gather X rows (bf16, 16B chunks). Rows 200..207 zero.
    for (int i = tid; i < 208 * 32; i += 416) {
        int n = i >> 5, q = i & 31;
        uint4 v = make_uint4(0u, 0u, 0u, 0u);
        if (n < 200) {
            int idx = conn[(b * NN + n) * 2 + (q >> 4)];
            v = *reinterpret_cast<const uint4*>(g_embB + (size_t)idx * 128 + (q & 15) * 8);
        }
        *reinterpret_cast<uint4*>(reinterpret_cast<char*>(Xs) + (n * XS + q * 8) * 2) = v;
    }

    int mrow = w * 16;
    // ldmatrix base addresses (byte offsets; row stride 528B)
    uint32_t xa_base = sX + (uint32_t)((mrow + (lane & 15)) * XS + (lane >> 4) * 8) * 2;
    uint32_t wb_lrow = (uint32_t)((lane & 7) * XS + ((lane >> 3) & 1) * 8) * 2;

    int r0 = mrow + (lane >> 2);
    int d0 = (lane & 3) * 2;

    for (int t = 0; t < 8; t++) {
        __syncthreads();   // previous tile's mma done before Ws overwrite
        for (int i = tid; i < 4096; i += 416) {
            int rn = i >> 5, q = i & 31;
            uint4 v = *reinterpret_cast<const uint4*>(g_Wb + ((size_t)t << 15) + rn * 256 + q * 8);
            *reinterpret_cast<uint4*>(WsB + (rn * XS + q * 8) * 2) = v;
        }
        __syncthreads();

        float c[16][4];
#pragma unroll
        for (int f = 0; f < 16; f++) { c[f][0] = 0.f; c[f][1] = 0.f; c[f][2] = 0.f; c[f][3] = 0.f; }

        for (int ks = 0; ks < 16; ks++) {
            uint32_t a[4];
            ldsm_x4(a, xa_base + ks * 32);
            uint32_t bcur[2], bnxt[2];
            ldsm_x2(bcur, sW + wb_lrow + ks * 32);
#pragma unroll
            for (int f = 0; f < 16; f++) {
                if (f < 15) ldsm_x2(bnxt, sW + wb_lrow + (f + 1) * (8 * XS * 2) + ks * 32);
                mma_bf16(c[f], a, bcur);
                bcur[0] = bnxt[0]; bcur[1] = bnxt[1];
            }
        }

        // epilogue: bf16 store to g_Kb/g_Qb
        int kq = t >> 2, h = t & 3;
        __nv_bfloat16* gdst = (kq ? g_Qb : g_Kb) + ((size_t)(sid * 4 + h)) * (NN * DD);
#pragma unroll
        for (int f = 0; f < 16; f++) {
            if (r0 < 200)
                *reinterpret_cast<uint32_t*>(gdst + (size_t)r0 * DD + f * 8 + d0) = pack_bf2(c[f][0], c[f][1]);
            if (r0 + 8 < 200)
                *reinterpret_cast<uint32_t*>(gdst + (size_t)(r0 + 8) * DD + f * 8 + d0) = pack_bf2(c[f][2], c[f][3]);
        }
    }
}

// ---------------- kernel 2: scores via mma.sync + softmax + column sums ----------
// CTA = (b,side,head), 416 threads = 13 warps. Ks/Qs bf16 [208][136].
#define KQS 136
#define SMA_Q_OFF  56576    // 208*136*2
#define SMA_WS_OFF 113152
#define SMA_MSK_OFF 113984
#define SMA_TOTAL  114816
__global__ void __launch_bounds__(416, 1)
attn_hmma(const int* __restrict__ lconn, const int* __restrict__ rconn) {
    extern __shared__ char smem[];
    uint32_t sK = smem_u32(smem);
    uint32_t sQ = sK + SMA_Q_OFF;
    float* ws  = reinterpret_cast<float*>(smem + SMA_WS_OFF);
    float* msk = reinterpret_cast<float*>(smem + SMA_MSK_OFF);

    int sid = blockIdx.x, h = blockIdx.y;
    int b = sid >> 1;
    const int* conn = (sid & 1) ? rconn : lconn;
    const __nv_bfloat16* Kg = g_Kb + ((size_t)(sid * 4 + h)) * (NN * DD);
    const __nv_bfloat16* Qg = g_Qb + ((size_t)(sid * 4 + h)) * (NN * DD);
    int tid = threadIdx.x, w = tid >> 5, lane = tid & 31;

    for (int i = tid; i < 208 * 16; i += 416) {
        int n = i >> 4, q = i & 15;
        uint4 vk = make_uint4(0u, 0u, 0u, 0u), vq = vk;
        if (n < 200) {
            vk = *reinterpret_cast<const uint4*>(Kg + (size_t)n * DD + q * 8);
            vq = *reinterpret_cast<const uint4*>(Qg + (size_t)n * DD + q * 8);
        }
        *reinterpret_cast<uint4*>(smem + (n * KQS + q * 8) * 2) = vk;
        *reinterpret_cast<uint4*>(smem + SMA_Q_OFF + (n * KQS + q * 8) * 2) = vq;
    }
    for (int i = tid; i < 208; i += 416) {
        ws[i] = 0.f;
        msk[i] = (i < 200) ? ((conn[(b * NN + i) * 2] == PAD_IDX) ? 1.f : 0.f) : 1.f;
    }
    __syncthreads();

    // mma: A = K rows (n), B = Q rows (m), k = d
    uint32_t ka_base = sK + (uint32_t)((w * 16 + (lane & 15)) * KQS + (lane >> 4) * 8) * 2;
    uint32_t qb_lrow = (uint32_t)((lane & 7) * KQS + ((lane >> 3) & 1) * 8) * 2;

    float c[26][4];
#pragma unroll
    for (int f = 0; f < 26; f++) { c[f][0] = 0.f; c[f][1] = 0.f; c[f][2] = 0.f; c[f][3] = 0.f; }

    for (int ks = 0; ks < 8; ks++) {
        uint32_t a[4];
        ldsm_x4(a, ka_base + ks * 32);
        uint32_t bcur[2], bnxt[2];
        ldsm_x2(bcur, sQ + qb_lrow + ks * 32);
#pragma unroll
        for (int f = 0; f < 26; f++) {
            if (f < 25) ldsm_x2(bnxt, sQ + qb_lrow + (f + 1) * (8 * KQS * 2) + ks * 32);
            mma_bf16(c[f], a, bcur);
            bcur[0] = bnxt[0]; bcur[1] = bnxt[1];
        }
    }

    // masking + row softmax + column accumulation, per fragment
    const float scale = 0.08838834764831845f;   // 128^-0.5
    int n0 = w * 16 + (lane >> 2);
    int mc = (lane & 3) * 2;
#pragma unroll
    for (int p = 0; p < 2; p++) {
        int nn = n0 + p * 8;
        float rm = msk[nn];
        float rmax = -3.0e38f;
#pragma unroll
        for (int f = 0; f < 26; f++) {
#pragma unroll
            for (int j = 0; j < 2; j++) {
                int m = f * 8 + mc + j;
                float s;
                if (m >= 200)       s = -1e30f;
                else if (rm > 0.5f || msk[m] > 0.5f) s = -1e9f;
                else                s = c[f][2 * p + j] * scale;
                c[f][2 * p + j] = s;
                rmax = fmaxf(rmax, s);
            }
        }
        rmax = fmaxf(rmax, __shfl_xor_sync(0xffffffffu, rmax, 1));
        rmax = fmaxf(rmax, __shfl_xor_sync(0xffffffffu, rmax, 2));
        float Z = 0.f;
#pragma unroll
        for (int f = 0; f < 26; f++) {
#pragma unroll
            for (int j = 0; j < 2; j++) {
                float e = __expf(c[f][2 * p + j] - rmax);
                c[f][2 * p + j] = e;
                Z += e;
            }
        }
        Z += __shfl_xor_sync(0xffffffffu, Z, 1);
        Z += __shfl_xor_sync(0xffffffffu, Z, 2);
        float inv = (nn < 200) ? (1.f / Z) : 0.f;
#pragma unroll
        for (int f = 0; f < 26; f++) {
            c[f][2 * p + 0] *= inv;
            c[f][2 * p + 1] *= inv;
        }
    }
    // column sums: combine 2 rows, reduce across the 8 row-groups, atomicAdd
#pragma unroll
    for (int f = 0; f < 26; f++) {
#pragma unroll
        for (int j = 0; j < 2; j++) {
            float v = c[f][j] + c[f][2 + j];
            v += __shfl_xor_sync(0xffffffffu, v, 4);
            v += __shfl_xor_sync(0xffffffffu, v, 8);
            v += __shfl_xor_sync(0xffffffffu, v, 16);
            if ((lane >> 2) == 0) {
                int m = f * 8 + mc + j;
                if (m < 200) atomicAdd(ws + m, v);
            }
        }
    }
    __syncthreads();
    for (int i = tid; i < 200; i += 416)
        g_w[(size_t)sid * 800 + h * 200 + i] = ws[i];
}

// ---------------- kernel 3: y = w^T X, folded projections, relu, residual, LN ----
__global__ void __launch_bounds__(256)
final_kernel(const int* __restrict__ ep, const int* __restrict__ lconn,
             const int* __restrict__ rconn, const float* __restrict__ emb,
             const float* __restrict__ lnw, const float* __restrict__ lnb,
             float* __restrict__ out) {
    __shared__ float wsm[4 * 200];
    __shared__ int reli[200], enti[200];
    __shared__ float es[128];
    __shared__ float ys[4][256];
    __shared__ float redbuf[8];

    int sid = blockIdx.x;
    int b = sid >> 1, side = sid & 1;
    const int* conn = side ? rconn : lconn;
    int tid = threadIdx.x;

    for (int i = tid; i < 200; i += 256) {
        int2 cc = reinterpret_cast<const int2*>(conn)[b * NN + i];
        reli[i] = cc.x; enti[i] = cc.y;
    }
    for (int i = tid; i < 800; i += 256) wsm[i] = g_w[(size_t)sid * 800 + i];
    if (tid < 128) es[tid] = emb[(size_t)ep[b * 2 + side] * DD + tid];
    __syncthreads();

    {
        float a0 = 0.f, a1 = 0.f, a2 = 0.f, a3 = 0.f;
        bool lo = tid < 128;
        int fo = tid & 127;
        for (int m = 0; m < 200; m++) {
            int row = lo ? reli[m] : enti[m];
            float x = emb[(size_t)row * DD + fo];
            a0 = fmaf(wsm[m],       x, a0);
            a1 = fmaf(wsm[200 + m], x, a1);
            a2 = fmaf(wsm[400 + m], x, a2);
            a3 = fmaf(wsm[600 + m], x, a3);
        }
        ys[0][tid] = a0; ys[1][tid] = a1; ys[2][tid] = a2; ys[3][tid] = a3;
    }
    __syncthreads();

    float tval = 0.f;
    if (tid < 128) {
        int d = tid;
        float pa = 0.f;
#pragma unroll
        for (int hh = 0; hh < 4; hh++) {
            const float* wc = g_Wcomb + (size_t)(hh * 256) * 128 + d;
            const float* yy = ys[hh];
            for (int ff = 0; ff < 256; ff++)
                pa = fmaf(yy[ff], wc[ff * 128], pa);
        }
        float ht = 0.f;
        for (int e = 0; e < 128; e++) ht = fmaf(es[e], g_WheadT[e * 128 + d], ht);
        tval = fmaxf(pa + ht, 0.f) + es[d];
    }

    int lane = tid & 31, warp = tid >> 5;
    float v = tval;
#pragma unroll
    for (int off = 16; off; off >>= 1) v += __shfl_xor_sync(0xffffffffu, v, off);
    if (lane == 0) redbuf[warp] = v;
    __syncthreads();
    float tot = 0.f;
#pragma unroll
    for (int w2 = 0; w2 < 8; w2++) tot += redbuf[w2];
    float mu = tot * (1.f / 128.f);
    __syncthreads();

    float diff = (tid < 128) ? (tval - mu) : 0.f;
    float v2 = diff * diff;
#pragma unroll
    for (int off = 16; off; off >>= 1) v2 += __shfl_xor_sync(0xffffffffu, v2, off);
    if (lane == 0) redbuf[warp] = v2;
    __syncthreads();
    float tot2 = 0.f;
#pragma unroll
    for (int w2 = 0; w2 < 8; w2++) tot2 += redbuf[w2];
    float var = tot2 * (1.f / 128.f);

    if (tid < 128)
        out[(size_t)sid * 128 + tid] =
            diff * rsqrtf(var + 1e-5f) * lnw[tid] + lnb[tid];
}

// ---------------- launch ----------------
extern "C" void kernel_launch(void* const* d_in, const int* in_sizes, int n_in,
                              void* d_out, int out_size) {
    const int*   ep    = (const int*)d_in[0];
    const int*   lconn = (const int*)d_in[1];
    const int*   rconn = (const int*)d_in[3];
    const float* emb   = (const float*)d_in[5];
    const float* Wv    = (const float*)d_in[6];
    const float* Wk    = (const float*)d_in[7];
    const float* Wq    = (const float*)d_in[8];
    const float* Ww    = (const float*)d_in[9];
    const float* Whead = (const float*)d_in[10];
    const float* lnw   = (const float*)d_in[11];
    const float* lnb   = (const float*)d_in[12];
    float* out = (float*)d_out;

    const int B = in_sizes[0] / 2;          // 1024
    const int SIDES = 2 * B;                // 2048

    static bool attr_done = false;
    if (!attr_done) {
        cudaFuncSetAttribute(proj_hmma, cudaFuncAttributeMaxDynamicSharedMemorySize, SMP_TOTAL);
        cudaFuncSetAttribute(attn_hmma, cudaFuncAttributeMaxDynamicSharedMemorySize, SMA_TOTAL);
        attr_done = true;
    }

    prep_wcomb<<<dim3(256, 4), 128>>>(Wv, Ww);
    prep_wheadT<<<128, 128>>>(Whead);
    prep_wbf16<<<1024, 256>>>(Wk, Wq);
    prep_embB<<<(VP1 * 128 + 255) / 256, 256>>>(emb);

    proj_hmma<<<SIDES, 416, SMP_TOTAL>>>(lconn, rconn);
    attn_hmma<<<dim3(SIDES, 4), 416, SMA_TOTAL>>>(lconn, rconn);
    final_kernel<<<SIDES, 256>>>(ep, lconn, rconn, emb, lnw, lnb, out);
}

// round 9
// speedup vs baseline: 4.6081x; 1.1770x over previous
#include <cuda_runtime.h>
#include <cuda_bf16.h>
#include <math.h>
#include <stdint.h>

#define NN 200
#define DD 128
#define PAD_IDX 100000
#define VP1 100001

// ---------------- device scratch (no runtime allocation allowed) ----------------
__device__ __nv_bfloat16 g_embB[(size_t)VP1 * 128];   // bf16 embeddings (25.6 MB)
__device__ uint2 g_Wfrag[8 * 16 * 16 * 32];           // pre-shuffled B fragments (512 KB)
__device__ float g_Wcomb[4 * 256 * 128];              // [h][f][d] Wv folded with Ww
__device__ float g_WheadT[128 * 128];                 // [e][d] Whead transposed

// ================= helpers =================
__device__ __forceinline__ uint32_t smem_u32(const void* p) {
    uint32_t a;
    asm("{ .reg .u64 t; cvta.to.shared.u64 t, %1; cvt.u32.u64 %0, t; }" : "=r"(a) : "l"(p));
    return a;
}
__device__ __forceinline__ void ldsm_x4(uint32_t* r, uint32_t a) {
    asm volatile("ldmatrix.sync.aligned.m8n8.x4.shared.b16 {%0,%1,%2,%3}, [%4];"
                 : "=r"(r[0]), "=r"(r[1]), "=r"(r[2]), "=r"(r[3]) : "r"(a));
}
__device__ __forceinline__ void ldsm_x2(uint32_t* r, uint32_t a) {
    asm volatile("ldmatrix.sync.aligned.m8n8.x2.shared.b16 {%0,%1}, [%2];"
                 : "=r"(r[0]), "=r"(r[1]) : "r"(a));
}
__device__ __forceinline__ void mma_bf16(float* c, const uint32_t* a, const uint32_t* b) {
    asm volatile("mma.sync.aligned.m16n8k16.row.col.f32.bf16.bf16.f32 "
                 "{%0,%1,%2,%3}, {%4,%5,%6,%7}, {%8,%9}, {%0,%1,%2,%3};"
                 : "+f"(c[0]), "+f"(c[1]), "+f"(c[2]), "+f"(c[3])
                 : "r"(a[0]), "r"(a[1]), "r"(a[2]), "r"(a[3]), "r"(b[0]), "r"(b[1]));
}
__device__ __forceinline__ uint32_t pack_bf2(float x, float y) {
    __nv_bfloat162 h = __floats2bfloat162_rn(x, y);
    return *reinterpret_cast<uint32_t*>(&h);
}

// ---------------- prep kernels ----------------
__global__ void prep_wcomb(const float* __restrict__ Wv, const float* __restrict__ Ww) {
    int f = blockIdx.x, h = blockIdx.y, d2 = threadIdx.x;
    float a = 0.f;
    for (int d = 0; d < 128; d++)
        a = fmaf(Wv[(h * 128 + d) * 256 + f], Ww[d2 * 512 + h * 128 + d], a);
    g_Wcomb[(h * 256 + f) * 128 + d2] = a;
}
__global__ void prep_wheadT(const float* __restrict__ Whead) {
    g_WheadT[blockIdx.x * 128 + threadIdx.x] = Whead[threadIdx.x * 128 + blockIdx.x];
}
__global__ void prep_embB(const float* __restrict__ emb) {
    size_t i = ((size_t)blockIdx.x * 256 + threadIdx.x) * 8;
    if (i < (size_t)VP1 * 128) {
        float4 v0 = *reinterpret_cast<const float4*>(emb + i);
        float4 v1 = *reinterpret_cast<const float4*>(emb + i + 4);
        uint4 o;
        o.x = pack_bf2(v0.x, v0.y); o.y = pack_bf2(v0.z, v0.w);
        o.z = pack_bf2(v1.x, v1.y); o.w = pack_bf2(v1.z, v1.w);
        *reinterpret_cast<uint4*>(g_embB + i) = o;
    }
}
// Pre-shuffle W into mma B-fragment layout: run the exact ldmatrix path once,
// dump each lane's 2 regs to g_Wfrag[t][ks][f][lane]. CTA = (t, ks), 1 warp.
__global__ void prep_wfrag(const float* __restrict__ Wk, const float* __restrict__ Wq) {
    __shared__ __nv_bfloat16 Wsh[128 * 24];   // stride 24 bf16 = 48B (ldsm conflict-free)
    int t = blockIdx.x, ks = blockIdx.y, lane = threadIdx.x;
    const float* Wsrc = ((t < 4) ? Wk : Wq) + (size_t)(t & 3) * 128 * 256;
    for (int i = lane; i < 256; i += 32) {
        int rn = i >> 1, q = (i & 1) * 8;
        const float* s = Wsrc + rn * 256 + ks * 16 + q;
        float4 v0 = *reinterpret_cast<const float4*>(s);
        float4 v1 = *reinterpret_cast<const float4*>(s + 4);
        uint4 o;
        o.x = pack_bf2(v0.x, v0.y); o.y = pack_bf2(v0.z, v0.w);
        o.z = pack_bf2(v1.x, v1.y); o.w = pack_bf2(v1.z, v1.w);
        *reinterpret_cast<uint4*>(&Wsh[rn * 24 + q]) = o;
    }
    __syncwarp();
    uint32_t base = smem_u32(Wsh) + (uint32_t)((lane & 7) * 24 + ((lane >> 3) & 1) * 8) * 2;
    for (int f = 0; f < 16; f++) {
        uint32_t bb[2];
        ldsm_x2(bb, base + f * (8 * 24 * 2));
        g_Wfrag[((t * 16 + ks) * 16 + f) * 32 + lane] = make_uint2(bb[0], bb[1]);
    }
}

// ---------------- the fused mega-kernel ----------------
// CTA = (b,side), 416 threads = 13 warps. Per head h: proj K_h,Q_h (mma.sync,
// B frags from g_Wfrag) -> SMEM; attention fragments + softmax + column sums;
// y_h = w^T X gathered from FP32 emb (bf16 X would lose ~2e-3 rel due to
// cancellation in the near-uniform weighted mean — measured in R8). Tail:
// folded Wcomb/Whead matvecs, relu, residual, LayerNorm -> out.
#define XS  264
#define KQS 136
#define OFF_X   0
#define OFF_K   109824
#define OFF_Q   166400
#define OFF_WS  222976
#define OFF_MSK 223808
#define OFF_YS  224640
#define OFF_ES  228736
#define OFF_PA2 229248
#define OFF_RED 230272
#define OFF_IDX 230336      // reli[200] + enti[200] ints
#define SM_TOT  231936

__global__ void __launch_bounds__(416, 1)
mega(const int* __restrict__ ep, const int* __restrict__ lconn,
     const int* __restrict__ rconn, const float* __restrict__ emb,
     const float* __restrict__ lnw, const float* __restrict__ lnb,
     float* __restrict__ out) {
    extern __shared__ char smem[];
    uint32_t sb = smem_u32(smem);
    float* ws  = reinterpret_cast<float*>(smem + OFF_WS);
    float* msk = reinterpret_cast<float*>(smem + OFF_MSK);
    float* ysm = reinterpret_cast<float*>(smem + OFF_YS);
    float* es  = reinterpret_cast<float*>(smem + OFF_ES);
    float* pa2 = reinterpret_cast<float*>(smem + OFF_PA2);
    float* red = reinterpret_cast<float*>(smem + OFF_RED);
    int*   reli = reinterpret_cast<int*>(smem + OFF_IDX);
    int*   enti = reli + 200;

    int tid = threadIdx.x, w = tid >> 5, lane = tid & 31;
    int sid = blockIdx.x, b = sid >> 1;
    const int* conn = (sid & 1) ? rconn : lconn;

    // gather X (rows >= 200 zeroed)
    for (int i = tid; i < 208 * 32; i += 416) {
        int n = i >> 5, q = i & 31;
        uint4 v = make_uint4(0u, 0u, 0u, 0u);
        if (n < 200) {
            int idx = conn[(b * NN + n) * 2 + (q >> 4)];
            v = *reinterpret_cast<const uint4*>(g_embB + (size_t)idx * 128 + (q & 15) * 8);
        }
        *reinterpret_cast<uint4*>(smem + OFF_X + (n * XS + q * 8) * 2) = v;
    }
    for (int i = tid; i < 208; i += 416) {
        ws[i] = 0.f;
        if (i < 200) {
            int2 cc = reinterpret_cast<const int2*>(conn)[b * NN + i];
            reli[i] = cc.x; enti[i] = cc.y;
            msk[i] = (cc.x == PAD_IDX) ? 1.f : 0.f;
        } else {
            msk[i] = 1.f;
        }
    }
    for (int i = tid; i < 1024; i += 416) ysm[i] = 0.f;
    if (tid < 128) es[tid] = emb[(size_t)ep[b * 2 + (sid & 1)] * DD + tid];
    __syncthreads();

    uint32_t xa = sb + OFF_X + (uint32_t)((w * 16 + (lane & 15)) * XS + (lane >> 4) * 8) * 2;
    uint32_t ka = sb + OFF_K + (uint32_t)((w * 16 + (lane & 15)) * KQS + (lane >> 4) * 8) * 2;
    uint32_t qb = sb + OFF_Q + (uint32_t)((lane & 7) * KQS + ((lane >> 3) & 1) * 8) * 2;
    int r0 = w * 16 + (lane >> 2);
    int d0 = (lane & 3) * 2;
    const float scale = 0.08838834764831845f;   // 128^-0.5

    for (int h = 0; h < 4; h++) {
        // ---- project K_h (kq=0) and Q_h (kq=1) into SMEM ----
#pragma unroll
        for (int kq = 0; kq < 2; kq++) {
            int t = kq * 4 + h;
            const uint2* wf = g_Wfrag + (size_t)t * 8192 + lane;
            float c[16][4];
#pragma unroll
            for (int f = 0; f < 16; f++) { c[f][0] = 0.f; c[f][1] = 0.f; c[f][2] = 0.f; c[f][3] = 0.f; }
            for (int ks = 0; ks < 16; ks++) {
                uint32_t a[4];
                ldsm_x4(a, xa + ks * 32);
                const uint2* wfk = wf + ks * 512;
#pragma unroll
                for (int f = 0; f < 16; f++) {
                    uint2 bv = __ldg(wfk + f * 32);
                    uint32_t bb[2] = { bv.x, bv.y };
                    mma_bf16(c[f], a, bb);
                }
            }
            char* dst = smem + (kq ? OFF_Q : OFF_K);
#pragma unroll
            for (int f = 0; f < 16; f++) {
                *reinterpret_cast<uint32_t*>(dst + (r0 * KQS + f * 8 + d0) * 2) =
                    pack_bf2(c[f][0], c[f][1]);
                *reinterpret_cast<uint32_t*>(dst + ((r0 + 8) * KQS + f * 8 + d0) * 2) =
                    pack_bf2(c[f][2], c[f][3]);
            }
        }
        __syncthreads();

        // ---- attention: scores, mask, softmax, column sums ----
        {
            float c[26][4];
#pragma unroll
            for (int f = 0; f < 26; f++) { c[f][0] = 0.f; c[f][1] = 0.f; c[f][2] = 0.f; c[f][3] = 0.f; }
            for (int ks = 0; ks < 8; ks++) {
                uint32_t a[4];
                ldsm_x4(a, ka + ks * 32);
                uint32_t bcur[2], bnxt[2];
                ldsm_x2(bcur, qb + ks * 32);
#pragma unroll
                for (int f = 0; f < 26; f++) {
                    if (f < 25) ldsm_x2(bnxt, qb + (f + 1) * (8 * KQS * 2) + ks * 32);
                    mma_bf16(c[f], a, bcur);
                    bcur[0] = bnxt[0]; bcur[1] = bnxt[1];
                }
            }
            int n0 = w * 16 + (lane >> 2);
            int mc = (lane & 3) * 2;
#pragma unroll
            for (int p = 0; p < 2; p++) {
                int nn = n0 + p * 8;
                float rm = msk[nn];
                float rmax = -3.0e38f;
#pragma unroll
                for (int f = 0; f < 26; f++) {
#pragma unroll
                    for (int j = 0; j < 2; j++) {
                        int m = f * 8 + mc + j;
                        float s;
                        if (m >= 200)                        s = -1e30f;
                        else if (rm > 0.5f || msk[m] > 0.5f) s = -1e9f;
                        else                                 s = c[f][2 * p + j] * scale;
                        c[f][2 * p + j] = s;
                        rmax = fmaxf(rmax, s);
                    }
                }
                rmax = fmaxf(rmax, __shfl_xor_sync(0xffffffffu, rmax, 1));
                rmax = fmaxf(rmax, __shfl_xor_sync(0xffffffffu, rmax, 2));
                float Z = 0.f;
#pragma unroll
                for (int f = 0; f < 26; f++) {
#pragma unroll
                    for (int j = 0; j < 2; j++) {
                        float e = __expf(c[f][2 * p + j] - rmax);
                        c[f][2 * p + j] = e;
                        Z += e;
                    }
                }
                Z += __shfl_xor_sync(0xffffffffu, Z, 1);
                Z += __shfl_xor_sync(0xffffffffu, Z, 2);
                float inv = (nn < 200) ? (1.f / Z) : 0.f;
#pragma unroll
                for (int f = 0; f < 26; f++) {
                    c[f][2 * p + 0] *= inv;
                    c[f][2 * p + 1] *= inv;
                }
            }
#pragma unroll
            for (int f = 0; f < 26; f++) {
#pragma unroll
                for (int j = 0; j < 2; j++) {
                    float v = c[f][j] + c[f][2 + j];
                    v += __shfl_xor_sync(0xffffffffu, v, 4);
                    v += __shfl_xor_sync(0xffffffffu, v, 8);
                    v += __shfl_xor_sync(0xffffffffu, v, 16);
                    if ((lane >> 2) == 0) {
                        int m = f * 8 + mc + j;
                        if (m < 200) atomicAdd(ws + m, v);
                    }
                }
            }
        }
        __syncthreads();

        // ---- y_h[f] += sum_m ws[m] * emb_fp32[row(m)][f], 13 warps split m ----
        {
            float acc[8];
#pragma unroll
            for (int k = 0; k < 8; k++) acc[k] = 0.f;
            int m0 = w * 16;
#pragma unroll 4
            for (int i = 0; i < 16; i++) {
                int m = m0 + i;
                if (m < 200) {
                    float wm = ws[m];
                    const float* er = emb + (size_t)reli[m] * DD;
                    const float* ee = emb + (size_t)enti[m] * DD;
#pragma unroll
                    for (int k = 0; k < 4; k++) acc[k]     = fmaf(wm, er[lane + 32 * k], acc[k]);
#pragma unroll
                    for (int k = 0; k < 4; k++) acc[4 + k] = fmaf(wm, ee[lane + 32 * k], acc[4 + k]);
                }
            }
#pragma unroll
            for (int k = 0; k < 8; k++)
                atomicAdd(&ysm[h * 256 + lane + 32 * k], acc[k]);
        }
        __syncthreads();
        for (int i = tid; i < 208; i += 416) ws[i] = 0.f;
        // (next head's attn atomicAdds are ordered after the proj-end barrier)
    }
    __syncthreads();

    // ---- tail: pa = ys @ Wcomb, + es @ WheadT, relu, residual, LayerNorm ----
    if (tid < 256) {
        int hp = tid >> 7, d = tid & 127;
        float acc = 0.f;
#pragma unroll
        for (int hh = 2 * hp; hh < 2 * hp + 2; hh++) {
            const float* wc = g_Wcomb + (size_t)hh * 256 * 128 + d;
            const float* yy = ysm + hh * 256;
            for (int f = 0; f < 256; f++)
                acc = fmaf(yy[f], wc[f * 128], acc);
        }
        pa2[tid] = acc;
    }
    __syncthreads();

    float tval = 0.f;
    if (tid < 128) {
        float pa = pa2[tid] + pa2[128 + tid];
        float ht = 0.f;
        for (int e = 0; e < 128; e++)
            ht = fmaf(es[e], g_WheadT[e * 128 + tid], ht);
        tval = fmaxf(pa + ht, 0.f) + es[tid];
    }

    float v = tval;
#pragma unroll
    for (int off = 16; off; off >>= 1) v += __shfl_xor_sync(0xffffffffu, v, off);
    if (lane == 0) red[w] = v;
    __syncthreads();
    float tot = 0.f;
#pragma unroll
    for (int i = 0; i < 13; i++) tot += red[i];
    float mu = tot * (1.f / 128.f);
    __syncthreads();

    float diff = (tid < 128) ? (tval - mu) : 0.f;
    float v2 = diff * diff;
#pragma unroll
    for (int off = 16; off; off >>= 1) v2 += __shfl_xor_sync(0xffffffffu, v2, off);
    if (lane == 0) red[w] = v2;
    __syncthreads();
    float tot2 = 0.f;
#pragma unroll
    for (int i = 0; i < 13; i++) tot2 += red[i];
    float var = tot2 * (1.f / 128.f);

    if (tid < 128)
        out[(size_t)sid * 128 + tid] =
            diff * rsqrtf(var + 1e-5f) * lnw[tid] + lnb[tid];
}

// ---------------- launch ----------------
extern "C" void kernel_launch(void* const* d_in, const int* in_sizes, int n_in,
                              void* d_out, int out_size) {
    const int*   ep    = (const int*)d_in[0];
    const int*   lconn = (const int*)d_in[1];
    const int*   rconn = (const int*)d_in[3];
    const float* emb   = (const float*)d_in[5];
    const float* Wv    = (const float*)d_in[6];
    const float* Wk    = (const float*)d_in[7];
    const float* Wq    = (const float*)d_in[8];
    const float* Ww    = (const float*)d_in[9];
    const float* Whead = (const float*)d_in[10];
    const float* lnw   = (const float*)d_in[11];
    const float* lnb   = (const float*)d_in[12];
    float* out = (float*)d_out;

    const int B = in_sizes[0] / 2;          // 1024
    const int SIDES = 2 * B;                // 2048

    static bool attr_done = false;
    if (!attr_done) {
        cudaFuncSetAttribute(mega, cudaFuncAttributeMaxDynamicSharedMemorySize, SM_TOT);
        attr_done = true;
    }

    prep_wcomb<<<dim3(256, 4), 128>>>(Wv, Ww);
    prep_wheadT<<<128, 128>>>(Whead);
    prep_embB<<<(int)(((size_t)VP1 * 128 / 8 + 255) / 256), 256>>>(emb);
    prep_wfrag<<<dim3(8, 16), 32>>>(Wk, Wq);

    mega<<<SIDES, 416, SM_TOT>>>(ep, lconn, rconn, emb, lnw, lnb, out);
}